// round 1
// baseline (speedup 1.0000x reference)
#include <cuda_runtime.h>
#include <math.h>

#define FS        100.0f
#define N_FILT    12
#define N_CH      27
#define FILT_DIM  5
#define BATCH     8
#define T_IN      65536
#define T_OUT     (T_IN - FILT_DIM + 1)   // 65532
#define NVEC      (T_OUT / 4)             // 16383 float4 output positions per row
#define TWO_PI    6.283185307179586f

// Filter bank scratch: 324 filters x 5 taps
__device__ float g_filters[N_CH * N_FILT * FILT_DIM];

// ---------------------------------------------------------------------------
// Kernel 1: build the sinc band-pass filter bank (matches the JAX reference)
// ---------------------------------------------------------------------------
__global__ void build_filters_kernel(const float* __restrict__ filt_low,
                                     const float* __restrict__ filt_band)
{
    int tid = threadIdx.x;            // 0..323 : tid = c*N_FILT + f
    if (tid >= N_CH * N_FILT) return;

    float lowv  = filt_low[tid];
    float bandv = filt_band[tid];

    float beg = fabsf(lowv) + (1.0f / FS);       // MIN_FREQ / FS
    float end = beg + fabsf(bandv);

    // t_right = [1.0, 2.0] / FS ; arg = 2*pi*FS*freq*t = [2*pi*freq, 4*pi*freq]
    // low_pass taps (len 5): 2*freq * [yr1, yr0, 1, yr0, yr1]
    auto lp = [](float freq, float out[FILT_DIM]) {
        float t0 = 1.0f / FS;        // matches f32 rounding of 0.01
        float t1 = 2.0f / FS;
        float a0 = (TWO_PI * FS) * freq * t0;
        float a1 = (TWO_PI * FS) * freq * t1;
        float y0 = sinf(a0) / a0;
        float y1 = sinf(a1) / a1;
        float s  = 2.0f * freq;
        out[0] = s * y1;
        out[1] = s * y0;
        out[2] = s * 1.0f;
        out[3] = s * y0;
        out[4] = s * y1;
    };

    float lpe[FILT_DIM], lpb[FILT_DIM], bp[FILT_DIM];
    lp(end, lpe);
    lp(beg, lpb);

    float mx = -INFINITY;
    #pragma unroll
    for (int k = 0; k < FILT_DIM; k++) {
        bp[k] = lpe[k] - lpb[k];
        mx = fmaxf(mx, bp[k]);
    }

    // window: n = linspace(0, 5, 5) = j*1.25
    #pragma unroll
    for (int k = 0; k < FILT_DIM; k++) {
        float n = (float)k * ((float)FILT_DIM / (float)(FILT_DIM - 1));
        float w = 0.42f - 0.5f * cosf(TWO_PI * n / (float)FILT_DIM)
                        + 0.08f * cosf(2.0f * TWO_PI * n / (float)FILT_DIM);
        g_filters[tid * FILT_DIM + k] = (bp[k] / mx) * w;
    }
}

// ---------------------------------------------------------------------------
// Kernel 2: grouped conv. Each block: one (b, c) pair + a chunk of positions.
// Thread handles 4 consecutive outputs for all 12 filters of channel c.
// ---------------------------------------------------------------------------
__global__ __launch_bounds__(256, 4)
void sinc_conv_kernel(const float* __restrict__ x, float* __restrict__ out)
{
    const int c = blockIdx.y;
    const int b = blockIdx.z;

    __shared__ float sf[N_FILT * FILT_DIM];   // 60 floats for this channel
    if (threadIdx.x < N_FILT * FILT_DIM)
        sf[threadIdx.x] = g_filters[c * (N_FILT * FILT_DIM) + threadIdx.x];
    __syncthreads();

    const int i = blockIdx.x * blockDim.x + threadIdx.x;   // float4 position
    if (i >= NVEC) return;

    const float4* x4 = (const float4*)(x + ((size_t)b * N_CH + c) * T_IN);
    float4 v0 = x4[i];
    float4 v1 = x4[i + 1];   // i <= 16382 -> i+1 <= 16383, covers x[65532..65535]

    const size_t t0 = (size_t)i * 4;
    float* orow = out + (((size_t)b * (N_CH * N_FILT)) + (size_t)c * N_FILT) * T_OUT + t0;

    #pragma unroll
    for (int f = 0; f < N_FILT; f++) {
        const float w0 = sf[f * FILT_DIM + 0];
        const float w1 = sf[f * FILT_DIM + 1];
        const float w2 = sf[f * FILT_DIM + 2];
        const float w3 = sf[f * FILT_DIM + 3];
        const float w4 = sf[f * FILT_DIM + 4];

        float4 r;
        r.x = w0*v0.x + w1*v0.y + w2*v0.z + w3*v0.w + w4*v1.x;
        r.y = w0*v0.y + w1*v0.z + w2*v0.w + w3*v1.x + w4*v1.y;
        r.z = w0*v0.z + w1*v0.w + w2*v1.x + w3*v1.y + w4*v1.z;
        r.w = w0*v0.w + w1*v1.x + w2*v1.y + w3*v1.z + w4*v1.w;

        *(float4*)(orow + (size_t)f * T_OUT) = r;
    }
}

extern "C" void kernel_launch(void* const* d_in, const int* in_sizes, int n_in,
                              void* d_out, int out_size)
{
    const float* x         = (const float*)d_in[0];
    const float* filt_low  = (const float*)d_in[1];
    const float* filt_band = (const float*)d_in[2];
    float* out             = (float*)d_out;

    build_filters_kernel<<<1, N_CH * N_FILT>>>(filt_low, filt_band);

    dim3 grid((NVEC + 255) / 256, N_CH, BATCH);
    sinc_conv_kernel<<<grid, 256>>>(x, out);
}